// round 1
// baseline (speedup 1.0000x reference)
#include <cuda_runtime.h>
#include <cuda_bf16.h>
#include <math.h>

// Problem constants
#define BATCH   8192
#define DMODEL  1024
#define DFF     4096
#define KPATH   4
#define RANK    16
#define HD      512

// ---------------- scratch (device globals; no allocation allowed) ----------
__device__ float g_W1[KPATH * DMODEL * DFF];   // [k][1024][4096]  64MB
__device__ float g_W2[KPATH * DFF * DMODEL];   // [k][4096][1024]  64MB
__device__ float g_xhd[BATCH * HD];            // 16MB
__device__ float g_probs[BATCH * KPATH];
__device__ float g_h[BATCH * DFF];             // 128MB (reused per path)
__device__ float g_y[BATCH * DMODEL];          // 32MB (reused per path)
__device__ float g_col[BATCH * HD];            // 16MB

// ---------------- W1 / W2 construction -------------------------------------
__global__ void build_w1(const float* __restrict__ c1a, const float* __restrict__ c1b) {
    int idx = blockIdx.x * blockDim.x + threadIdx.x;
    if (idx >= KPATH * DMODEL * DFF) return;
    int no = idx & (DFF - 1);
    int t  = idx >> 12;               // /4096
    int mp = t & (DMODEL - 1);
    int k  = t >> 10;
    int m = mp >> 5, p = mp & 31;
    int n = no >> 6, o = no & 63;
    const float* a = c1a + (((k * 32 + m) * 64 + n) * 16);
    const float* b = c1b + ((size_t)(k * 16) * 32 + p) * 64 + o;   // stride per r = 32*64
    float s = 0.f;
#pragma unroll
    for (int r = 0; r < RANK; r++) s += a[r] * b[(size_t)r * 32 * 64];
    g_W1[idx] = s;
}

__global__ void build_w2(const float* __restrict__ c2a, const float* __restrict__ c2b) {
    int idx = blockIdx.x * blockDim.x + threadIdx.x;
    if (idx >= KPATH * DFF * DMODEL) return;
    int no = idx & (DMODEL - 1);
    int t  = idx >> 10;               // /1024
    int mp = t & (DFF - 1);
    int k  = t >> 12;
    int m = mp >> 6, p = mp & 63;
    int n = no >> 5, o = no & 31;
    const float* a = c2a + (((k * 64 + m) * 32 + n) * 16);
    const float* b = c2b + ((size_t)(k * 16) * 64 + p) * 32 + o;   // stride per r = 64*32
    float s = 0.f;
#pragma unroll
    for (int r = 0; r < RANK; r++) s += a[r] * b[(size_t)r * 64 * 32];
    g_W2[idx] = s;
}

// ---------------- routing softmax -------------------------------------------
__global__ void routing_kernel(const float* __restrict__ pb) {
    int gid  = blockIdx.x * blockDim.x + threadIdx.x;
    int warp = gid >> 5;
    int lane = gid & 31;
    if (warp >= BATCH) return;
    const float* xr = g_xhd + (size_t)warp * HD;
    float sc[KPATH];
#pragma unroll
    for (int k = 0; k < KPATH; k++) {
        float s = 0.f;
        for (int h = lane; h < HD; h += 32) s += xr[h] * pb[k * HD + h];
#pragma unroll
        for (int off = 16; off; off >>= 1) s += __shfl_xor_sync(0xffffffffu, s, off);
        sc[k] = s;
    }
    if (lane == 0) {
        float mx = fmaxf(fmaxf(sc[0], sc[1]), fmaxf(sc[2], sc[3]));
        float e0 = expf(sc[0] - mx), e1 = expf(sc[1] - mx);
        float e2 = expf(sc[2] - mx), e3 = expf(sc[3] - mx);
        float inv = 1.0f / (e0 + e1 + e2 + e3);
        g_probs[warp * 4 + 0] = e0 * inv;
        g_probs[warp * 4 + 1] = e1 * inv;
        g_probs[warp * 4 + 2] = e2 * inv;
        g_probs[warp * 4 + 3] = e3 * inv;
    }
}

// ---------------- tiled SGEMM -----------------------------------------------
#define BM 128
#define BN 128
#define BKT 16
#define TM 8
#define TN 8

__device__ __forceinline__ float gelu_tanh(float v) {
    float u = 0.7978845608028654f * (v + 0.044715f * v * v * v);
    return 0.5f * v * (1.0f + tanhf(u));
}

// EPI: 0 = none, 1 = gelu, 2 = bind-accumulate (probs * pw scale, += into C)
template <int EPI>
__global__ __launch_bounds__(256, 2)
void sgemm(const float* __restrict__ A, const float* __restrict__ B,
           float* __restrict__ C, int M, int N, int Kd,
           const float* __restrict__ pw, int kpath)
{
    __shared__ float As[BKT][BM];
    __shared__ float Bs[BKT][BN];

    int tid = threadIdx.x;
    int tx = tid & 15;     // 0..15 (col group)
    int ty = tid >> 4;     // 0..15 (row group)

    const float* Ab = A + (size_t)blockIdx.y * BM * Kd;
    const float* Bb = B + (size_t)blockIdx.x * BN;

    float acc[TM][TN];
#pragma unroll
    for (int i = 0; i < TM; i++)
#pragma unroll
        for (int j = 0; j < TN; j++) acc[i][j] = 0.f;

    for (int k0 = 0; k0 < Kd; k0 += BKT) {
        // A tile: 128 rows x 16 cols = 512 float4 loads; 2 per thread
#pragma unroll
        for (int i = 0; i < 2; i++) {
            int l = tid * 2 + i;
            int row = l >> 2;          // 0..127
            int col = (l & 3) * 4;     // 0,4,8,12
            float4 v = *(const float4*)(Ab + (size_t)row * Kd + k0 + col);
            As[col + 0][row] = v.x;
            As[col + 1][row] = v.y;
            As[col + 2][row] = v.z;
            As[col + 3][row] = v.w;
        }
        // B tile: 16 rows x 128 cols = 512 float4 loads; 2 per thread
#pragma unroll
        for (int i = 0; i < 2; i++) {
            int l = tid * 2 + i;
            int row = l >> 5;           // 0..15
            int col = (l & 31) * 4;     // 0..124
            *(float4*)&Bs[row][col] = *(const float4*)(Bb + (size_t)(k0 + row) * N + col);
        }
        __syncthreads();

#pragma unroll
        for (int kk = 0; kk < BKT; kk++) {
            float a[TM], b[TN];
#pragma unroll
            for (int i = 0; i < TM; i++) a[i] = As[kk][ty * TM + i];
            float4 b0 = *(float4*)&Bs[kk][tx * TN];
            float4 b1 = *(float4*)&Bs[kk][tx * TN + 4];
            b[0] = b0.x; b[1] = b0.y; b[2] = b0.z; b[3] = b0.w;
            b[4] = b1.x; b[5] = b1.y; b[6] = b1.z; b[7] = b1.w;
#pragma unroll
            for (int i = 0; i < TM; i++)
#pragma unroll
                for (int j = 0; j < TN; j++)
                    acc[i][j] += a[i] * b[j];
        }
        __syncthreads();
    }

    int row0 = blockIdx.y * BM + ty * TM;
    int col0 = blockIdx.x * BN + tx * TN;
#pragma unroll
    for (int i = 0; i < TM; i++) {
        int r = row0 + i;
        float pscale = 0.f;
        if (EPI == 2) pscale = g_probs[r * KPATH + kpath];
        float* Crow = C + (size_t)r * N + col0;
#pragma unroll
        for (int j = 0; j < TN; j++) {
            float v = acc[i][j];
            if (EPI == 1) v = gelu_tanh(v);
            if (EPI == 2) {
                v = v * pscale * pw[kpath * HD + col0 + j];
                if (kpath == 0) Crow[j] = v;
                else            Crow[j] += v;
            } else {
                Crow[j] = v;
            }
        }
    }
}

// ---------------- launch -----------------------------------------------------
extern "C" void kernel_launch(void* const* d_in, const int* in_sizes, int n_in,
                              void* d_out, int out_size)
{
    const float* x     = (const float*)d_in[0];
    const float* c1a   = (const float*)d_in[1];
    const float* c1b   = (const float*)d_in[2];
    const float* c2a   = (const float*)d_in[3];
    const float* c2b   = (const float*)d_in[4];
    const float* hd_in = (const float*)d_in[5];
    const float* hd_out= (const float*)d_in[6];
    const float* pb    = (const float*)d_in[7];
    const float* pw    = (const float*)d_in[8];
    float* out = (float*)d_out;

    float *W1, *W2, *xhd, *h, *y, *col;
    cudaGetSymbolAddress((void**)&W1,  g_W1);
    cudaGetSymbolAddress((void**)&W2,  g_W2);
    cudaGetSymbolAddress((void**)&xhd, g_xhd);
    cudaGetSymbolAddress((void**)&h,   g_h);
    cudaGetSymbolAddress((void**)&y,   g_y);
    cudaGetSymbolAddress((void**)&col, g_col);

    // 1. Build dense per-path weights from TT cores
    build_w1<<<(KPATH * DMODEL * DFF + 255) / 256, 256>>>(c1a, c1b);
    build_w2<<<(KPATH * DFF * DMODEL + 255) / 256, 256>>>(c2a, c2b);

    // 2. x_hd = x @ hd_in   [8192,512]
    {
        dim3 g(HD / BN, BATCH / BM);
        sgemm<0><<<g, 256>>>(x, hd_in, xhd, BATCH, HD, DMODEL, nullptr, 0);
    }

    // 3. routing probs (softmax over 4 paths)
    routing_kernel<<<(BATCH * 32 + 255) / 256, 256>>>(pb);

    // 4. per-path FFN + bind-accumulate into collapsed
    for (int k = 0; k < KPATH; k++) {
        {   // h = gelu(x @ W1_k)   [8192,4096]
            dim3 g(DFF / BN, BATCH / BM);
            sgemm<1><<<g, 256>>>(x, W1 + (size_t)k * DMODEL * DFF, h,
                                 BATCH, DFF, DMODEL, nullptr, 0);
        }
        {   // y = h @ W2_k   [8192,1024]
            dim3 g(DMODEL / BN, BATCH / BM);
            sgemm<0><<<g, 256>>>(h, W2 + (size_t)k * DFF * DMODEL, y,
                                 BATCH, DMODEL, DFF, nullptr, 0);
        }
        {   // col (+)= probs[:,k] * pw[k] o (y @ hd_in)   [8192,512]
            dim3 g(HD / BN, BATCH / BM);
            sgemm<2><<<g, 256>>>(y, hd_in, col, BATCH, HD, DMODEL, pw, k);
        }
    }

    // 5. out = col @ hd_out   [8192,1024]
    {
        dim3 g(DMODEL / BN, BATCH / BM);
        sgemm<0><<<g, 256>>>(col, hd_out, out, BATCH, DMODEL, HD, nullptr, 0);
    }
}

// round 3
// speedup vs baseline: 1.3124x; 1.3124x over previous
#include <cuda_runtime.h>
#include <math.h>
#include <stdint.h>

// Problem constants
#define BATCH   8192
#define DMODEL  1024
#define DFF     4096
#define KPATH   4
#define RANK    16
#define HD      512

// ---------------- scratch (device globals; no allocation allowed) ----------
__device__ float g_W1T[KPATH * DFF * DMODEL];   // [k][4096][1024] (N,K) 64MB
__device__ float g_W2T[KPATH * DMODEL * DFF];   // [k][1024][4096] (N,K) 64MB
__device__ float g_hdinT[HD * DMODEL];          // [512][1024]
__device__ float g_hdoutT[DMODEL * HD];         // [1024][512]
__device__ float g_xhd[BATCH * HD];
__device__ float g_probs[BATCH * KPATH];
__device__ float g_h[BATCH * DFF];              // 128MB
__device__ float g_y[BATCH * DMODEL];           // 32MB
__device__ float g_col[BATCH * HD];             // 16MB

// ---------------- W1T / W2T construction (transposed dense weights) ---------
__global__ void build_w1t(const float* __restrict__ c1a, const float* __restrict__ c1b) {
    int idx = blockIdx.x * blockDim.x + threadIdx.x;
    if (idx >= KPATH * DFF * DMODEL) return;
    int d  = idx & (DMODEL - 1);          // m*32+p
    int t  = idx >> 10;
    int nn = t & (DFF - 1);               // n*64+o
    int k  = t >> 12;
    int m = d >> 5, p = d & 31;
    int n = nn >> 6, o = nn & 63;
    const float* a = c1a + (((k * 32 + m) * 64 + n) * 16);
    const float* b = c1b + ((size_t)(k * 16) * 32 + p) * 64 + o;
    float s = 0.f;
#pragma unroll
    for (int r = 0; r < RANK; r++) s += a[r] * b[(size_t)r * 32 * 64];
    g_W1T[idx] = s;
}

__global__ void build_w2t(const float* __restrict__ c2a, const float* __restrict__ c2b) {
    int idx = blockIdx.x * blockDim.x + threadIdx.x;
    if (idx >= KPATH * DMODEL * DFF) return;
    int d  = idx & (DFF - 1);             // m*64+p
    int t  = idx >> 12;
    int nn = t & (DMODEL - 1);            // n*32+o
    int k  = t >> 10;
    int m = d >> 6, p = d & 63;
    int n = nn >> 5, o = nn & 31;
    const float* a = c2a + (((k * 64 + m) * 32 + n) * 16);
    const float* b = c2b + ((size_t)(k * 16) * 64 + p) * 32 + o;
    float s = 0.f;
#pragma unroll
    for (int r = 0; r < RANK; r++) s += a[r] * b[(size_t)r * 64 * 32];
    g_W2T[idx] = s;
}

__global__ void transpose_hdin(const float* __restrict__ hd_in) {
    int i = blockIdx.x * blockDim.x + threadIdx.x;
    if (i >= DMODEL * HD) return;
    int d = i / HD, h2 = i % HD;
    g_hdinT[(size_t)h2 * DMODEL + d] = hd_in[i];
}
__global__ void transpose_hdout(const float* __restrict__ hd_out) {
    int i = blockIdx.x * blockDim.x + threadIdx.x;
    if (i >= HD * DMODEL) return;
    int h2 = i / DMODEL, d = i % DMODEL;
    g_hdoutT[(size_t)d * HD + h2] = hd_out[i];
}

// ---------------- routing softmax -------------------------------------------
__global__ void routing_kernel(const float* __restrict__ pb) {
    int gid  = blockIdx.x * blockDim.x + threadIdx.x;
    int warp = gid >> 5;
    int lane = gid & 31;
    if (warp >= BATCH) return;
    const float* xr = g_xhd + (size_t)warp * HD;
    float sc[KPATH];
#pragma unroll
    for (int k = 0; k < KPATH; k++) {
        float s = 0.f;
        for (int h = lane; h < HD; h += 32) s += xr[h] * pb[k * HD + h];
#pragma unroll
        for (int off = 16; off; off >>= 1) s += __shfl_xor_sync(0xffffffffu, s, off);
        sc[k] = s;
    }
    if (lane == 0) {
        float mx = fmaxf(fmaxf(sc[0], sc[1]), fmaxf(sc[2], sc[3]));
        float e0 = expf(sc[0] - mx), e1 = expf(sc[1] - mx);
        float e2 = expf(sc[2] - mx), e3 = expf(sc[3] - mx);
        float inv = 1.0f / (e0 + e1 + e2 + e3);
        g_probs[warp * 4 + 0] = e0 * inv;
        g_probs[warp * 4 + 1] = e1 * inv;
        g_probs[warp * 4 + 2] = e2 * inv;
        g_probs[warp * 4 + 3] = e3 * inv;
    }
}

// ---------------- tf32 mma.sync GEMM ----------------------------------------
// C[M,N] = A[M,K] @ Bt[N,K]^T with tf32 tensor cores.
// CTA 128x128, BK=32, 256 threads (8 warps: 4 in M x 2 in N; warp tile 32x64).
#define BM 128
#define BN 128
#define BK 32
#define STAGES 4
#define PADF 4                         // pad floats per row
#define ROWF (BK + PADF)               // 36 floats
#define TILEB (BM * ROWF * 4)          // 18432 bytes per operand per stage
#define STAGEB (2 * TILEB)             // 36864
#define GEMM_SMEM (STAGES * STAGEB)    // 147456

__device__ __forceinline__ void cp16(uint32_t dst, const void* src) {
    asm volatile("cp.async.cg.shared.global [%0], [%1], 16;"
                 :: "r"(dst), "l"(src) : "memory");
}
__device__ __forceinline__ void cp_commit() {
    asm volatile("cp.async.commit_group;" ::: "memory");
}
template <int N>
__device__ __forceinline__ void cp_wait() {
    asm volatile("cp.async.wait_group %0;" :: "n"(N) : "memory");
}
__device__ __forceinline__ uint32_t f2tf32(float f) {
    uint32_t r;
    asm("cvt.rna.tf32.f32 %0, %1;" : "=r"(r) : "f"(f));
    return r;
}
__device__ __forceinline__ void mma_tf32(float* c, const uint32_t* a, const uint32_t* b) {
    asm volatile(
        "mma.sync.aligned.m16n8k8.row.col.f32.tf32.tf32.f32 "
        "{%0,%1,%2,%3}, {%4,%5,%6,%7}, {%8,%9}, {%0,%1,%2,%3};"
        : "+f"(c[0]), "+f"(c[1]), "+f"(c[2]), "+f"(c[3])
        : "r"(a[0]), "r"(a[1]), "r"(a[2]), "r"(a[3]), "r"(b[0]), "r"(b[1]));
}

__device__ __forceinline__ float gelu_tanh(float v) {
    float u = 0.7978845608028654f * (v + 0.044715f * v * v * v);
    return 0.5f * v * (1.0f + tanhf(u));
}

// EPI: 0 = none, 1 = gelu, 2 = bind-accumulate (probs * pw, += into C)
template <int EPI>
__global__ __launch_bounds__(256)
void tgemm(const float* __restrict__ A, const float* __restrict__ Bt,
           float* __restrict__ C, int M, int N, int Kd,
           const float* __restrict__ pw, int kpath)
{
    extern __shared__ float smem[];
    uint32_t sbase = (uint32_t)__cvta_generic_to_shared(smem);

    int tid  = threadIdx.x;
    int wid  = tid >> 5;
    int lane = tid & 31;
    int g    = lane >> 2;      // group 0..7
    int tig  = lane & 3;       // thread-in-group 0..3
    int wm   = wid & 3;        // warp M index 0..3 (32 rows each)
    int wn   = wid >> 2;       // warp N index 0..1 (64 cols each)

    const float* Ab = A  + (size_t)blockIdx.y * BM * Kd;
    const float* Bb = Bt + (size_t)blockIdx.x * BN * Kd;
    int KT = Kd / BK;

    float acc[2][8][4];
#pragma unroll
    for (int i = 0; i < 2; i++)
#pragma unroll
        for (int j = 0; j < 8; j++)
#pragma unroll
            for (int q = 0; q < 4; q++) acc[i][j][q] = 0.f;

    // ---- producer helper (4 A-chunks + 4 B-chunks of 16B per thread) ----
    auto load_stage = [&](int stage, int kt) {
        uint32_t abase = sbase + stage * STAGEB;
        uint32_t bbase = abase + TILEB;
        const float* As = Ab + kt * BK;
        const float* Bs = Bb + kt * BK;
#pragma unroll
        for (int i = 0; i < 4; i++) {
            int c   = tid + 256 * i;   // 0..1023
            int row = c >> 3;
            int c16 = c & 7;
            cp16(abase + row * (ROWF * 4) + c16 * 16,
                 As + (size_t)row * Kd + c16 * 4);
            cp16(bbase + row * (ROWF * 4) + c16 * 16,
                 Bs + (size_t)row * Kd + c16 * 4);
        }
    };

    // prologue: fill STAGES-1 stages
#pragma unroll
    for (int s = 0; s < STAGES - 1; s++) {
        if (s < KT) load_stage(s, s);
        cp_commit();
    }

    for (int kt = 0; kt < KT; kt++) {
        cp_wait<STAGES - 2>();
        __syncthreads();

        // prefetch next stage
        int nxt = kt + STAGES - 1;
        if (nxt < KT) load_stage(nxt % STAGES, nxt);
        cp_commit();

        // compute current stage
        int st = kt % STAGES;
        const float* As = smem + (size_t)st * (STAGEB / 4);
        const float* Bs = As + (TILEB / 4);

#pragma unroll
        for (int kk = 0; kk < 4; kk++) {
            int kcol = kk * 8 + tig;
            uint32_t afr[2][4];
#pragma unroll
            for (int mf = 0; mf < 2; mf++) {
                int r0 = wm * 32 + mf * 16 + g;
                afr[mf][0] = f2tf32(As[r0 * ROWF + kcol]);
                afr[mf][1] = f2tf32(As[(r0 + 8) * ROWF + kcol]);
                afr[mf][2] = f2tf32(As[r0 * ROWF + kcol + 4]);
                afr[mf][3] = f2tf32(As[(r0 + 8) * ROWF + kcol + 4]);
            }
            uint32_t bfr[8][2];
#pragma unroll
            for (int nf = 0; nf < 8; nf++) {
                int n0 = wn * 64 + nf * 8 + g;
                bfr[nf][0] = f2tf32(Bs[n0 * ROWF + kcol]);
                bfr[nf][1] = f2tf32(Bs[n0 * ROWF + kcol + 4]);
            }
#pragma unroll
            for (int mf = 0; mf < 2; mf++)
#pragma unroll
                for (int nf = 0; nf < 8; nf++)
                    mma_tf32(acc[mf][nf], afr[mf], bfr[nf]);
        }
        __syncthreads();
    }

    // ---- epilogue ----
#pragma unroll
    for (int mf = 0; mf < 2; mf++) {
        int row0 = blockIdx.y * BM + wm * 32 + mf * 16 + g;
#pragma unroll
        for (int half = 0; half < 2; half++) {     // c0,c1 then c2,c3 (row+8)
            int row = row0 + half * 8;
            float ps0 = 0.f;
            if (EPI == 2) ps0 = g_probs[row * KPATH + kpath];
            float* Crow = C + (size_t)row * N;
#pragma unroll
            for (int nf = 0; nf < 8; nf++) {
                int col = blockIdx.x * BN + wn * 64 + nf * 8 + 2 * tig;
                float v0 = acc[mf][nf][half * 2 + 0];
                float v1 = acc[mf][nf][half * 2 + 1];
                if (EPI == 1) { v0 = gelu_tanh(v0); v1 = gelu_tanh(v1); }
                if (EPI == 2) {
                    v0 = v0 * ps0 * pw[kpath * HD + col];
                    v1 = v1 * ps0 * pw[kpath * HD + col + 1];
                    if (kpath > 0) { v0 += Crow[col]; v1 += Crow[col + 1]; }
                }
                float2 v = make_float2(v0, v1);
                *(float2*)(Crow + col) = v;
            }
        }
    }
}

// ---------------- launch -----------------------------------------------------
extern "C" void kernel_launch(void* const* d_in, const int* in_sizes, int n_in,
                              void* d_out, int out_size)
{
    const float* x      = (const float*)d_in[0];
    const float* c1a    = (const float*)d_in[1];
    const float* c1b    = (const float*)d_in[2];
    const float* c2a    = (const float*)d_in[3];
    const float* c2b    = (const float*)d_in[4];
    const float* hd_in  = (const float*)d_in[5];
    const float* hd_out = (const float*)d_in[6];
    const float* pb     = (const float*)d_in[7];
    const float* pw     = (const float*)d_in[8];
    float* out = (float*)d_out;

    float *W1T, *W2T, *hdinT, *hdoutT, *xhd, *h, *y, *col;
    cudaGetSymbolAddress((void**)&W1T,    g_W1T);
    cudaGetSymbolAddress((void**)&W2T,    g_W2T);
    cudaGetSymbolAddress((void**)&hdinT,  g_hdinT);
    cudaGetSymbolAddress((void**)&hdoutT, g_hdoutT);
    cudaGetSymbolAddress((void**)&xhd,    g_xhd);
    cudaGetSymbolAddress((void**)&h,      g_h);
    cudaGetSymbolAddress((void**)&y,      g_y);
    cudaGetSymbolAddress((void**)&col,    g_col);

    static bool attr_set = false;
    if (!attr_set) {
        cudaFuncSetAttribute(tgemm<0>, cudaFuncAttributeMaxDynamicSharedMemorySize, GEMM_SMEM);
        cudaFuncSetAttribute(tgemm<1>, cudaFuncAttributeMaxDynamicSharedMemorySize, GEMM_SMEM);
        cudaFuncSetAttribute(tgemm<2>, cudaFuncAttributeMaxDynamicSharedMemorySize, GEMM_SMEM);
        attr_set = true;
    }

    // 1. Build transposed dense weights
    build_w1t<<<(KPATH * DFF * DMODEL + 255) / 256, 256>>>(c1a, c1b);
    build_w2t<<<(KPATH * DMODEL * DFF + 255) / 256, 256>>>(c2a, c2b);
    transpose_hdin<<<(DMODEL * HD + 255) / 256, 256>>>(hd_in);
    transpose_hdout<<<(HD * DMODEL + 255) / 256, 256>>>(hd_out);

    // 2. x_hd = x @ hd_in   [8192,512]
    tgemm<0><<<dim3(HD / BN, BATCH / BM), 256, GEMM_SMEM>>>(
        x, hdinT, xhd, BATCH, HD, DMODEL, nullptr, 0);

    // 3. routing probs
    routing_kernel<<<(BATCH * 32 + 255) / 256, 256>>>(pb);

    // 4. per-path FFN + bind-accumulate
    for (int k = 0; k < KPATH; k++) {
        tgemm<1><<<dim3(DFF / BN, BATCH / BM), 256, GEMM_SMEM>>>(
            x, W1T + (size_t)k * DFF * DMODEL, h, BATCH, DFF, DMODEL, nullptr, 0);
        tgemm<0><<<dim3(DMODEL / BN, BATCH / BM), 256, GEMM_SMEM>>>(
            h, W2T + (size_t)k * DMODEL * DFF, y, BATCH, DMODEL, DFF, nullptr, 0);
        tgemm<2><<<dim3(HD / BN, BATCH / BM), 256, GEMM_SMEM>>>(
            y, hdinT, col, BATCH, HD, DMODEL, pw, k);
    }

    // 5. out = col @ hd_out   [8192,1024]
    tgemm<0><<<dim3(DMODEL / BN, BATCH / BM), 256, GEMM_SMEM>>>(
        col, hdoutT, out, BATCH, DMODEL, HD, nullptr, 0);
}

// round 4
// speedup vs baseline: 3.6828x; 2.8061x over previous
#include <cuda_runtime.h>
#include <cuda_fp16.h>
#include <math.h>
#include <stdint.h>

// Problem constants
#define BATCH   8192
#define DMODEL  1024
#define DFF     4096
#define KPATH   4
#define RANK    16
#define HD      512

// ---------------- scratch (device globals; no allocation allowed) ----------
__device__ __half g_W1h[KPATH * DFF * DMODEL];   // [k][4096][1024] (N,K) fp16 32MB
__device__ __half g_W2h[KPATH * DMODEL * DFF];   // [k][1024][4096] (N,K) fp16 32MB
__device__ __half g_hdinTh[HD * DMODEL];         // [512][1024] fp16
__device__ __half g_hdoutTh[DMODEL * HD];        // [1024][512] fp16
__device__ __half g_xh[BATCH * DMODEL];          // x in fp16 16MB
__device__ __half g_h[BATCH * DFF];              // 64MB
__device__ __half g_y[BATCH * DMODEL];           // 16MB
__device__ __half g_colh[BATCH * HD];            // 8MB
__device__ float  g_xhd[BATCH * HD];             // fp32 for routing
__device__ float  g_col[BATCH * HD];             // fp32 accumulator
__device__ float  g_probs[BATCH * KPATH];

// ---------------- builders / converters -------------------------------------
__global__ void build_w1h(const float* __restrict__ c1a, const float* __restrict__ c1b) {
    int idx = blockIdx.x * blockDim.x + threadIdx.x;
    if (idx >= KPATH * DFF * DMODEL) return;
    int d  = idx & (DMODEL - 1);          // m*32+p
    int t  = idx >> 10;
    int nn = t & (DFF - 1);               // n*64+o
    int k  = t >> 12;
    int m = d >> 5, p = d & 31;
    int n = nn >> 6, o = nn & 63;
    const float* a = c1a + (((k * 32 + m) * 64 + n) * 16);
    const float* b = c1b + ((size_t)(k * 16) * 32 + p) * 64 + o;
    float s = 0.f;
#pragma unroll
    for (int r = 0; r < RANK; r++) s += a[r] * b[(size_t)r * 32 * 64];
    g_W1h[idx] = __float2half(s);
}

__global__ void build_w2h(const float* __restrict__ c2a, const float* __restrict__ c2b) {
    int idx = blockIdx.x * blockDim.x + threadIdx.x;
    if (idx >= KPATH * DMODEL * DFF) return;
    int d  = idx & (DFF - 1);             // m*64+p
    int t  = idx >> 12;
    int nn = t & (DMODEL - 1);            // n*32+o
    int k  = t >> 10;
    int m = d >> 6, p = d & 63;
    int n = nn >> 5, o = nn & 31;
    const float* a = c2a + (((k * 64 + m) * 32 + n) * 16);
    const float* b = c2b + ((size_t)(k * 16) * 64 + p) * 32 + o;
    float s = 0.f;
#pragma unroll
    for (int r = 0; r < RANK; r++) s += a[r] * b[(size_t)r * 64 * 32];
    g_W2h[idx] = __float2half(s);
}

__global__ void conv_x(const float* __restrict__ x) {
    int i = blockIdx.x * blockDim.x + threadIdx.x;
    if (i < BATCH * DMODEL) g_xh[i] = __float2half(x[i]);
}
__global__ void transpose_hdin(const float* __restrict__ hd_in) {
    int i = blockIdx.x * blockDim.x + threadIdx.x;
    if (i >= DMODEL * HD) return;
    int d = i / HD, h2 = i % HD;
    g_hdinTh[(size_t)h2 * DMODEL + d] = __float2half(hd_in[i]);
}
__global__ void transpose_hdout(const float* __restrict__ hd_out) {
    int i = blockIdx.x * blockDim.x + threadIdx.x;
    if (i >= HD * DMODEL) return;
    int h2 = i / DMODEL, d = i % DMODEL;
    g_hdoutTh[(size_t)d * HD + h2] = __float2half(hd_out[i]);
}
__global__ void conv_col() {
    int i = blockIdx.x * blockDim.x + threadIdx.x;
    if (i < BATCH * HD) g_colh[i] = __float2half(g_col[i]);
}

// ---------------- routing softmax -------------------------------------------
__global__ void routing_kernel(const float* __restrict__ pb) {
    int gid  = blockIdx.x * blockDim.x + threadIdx.x;
    int warp = gid >> 5;
    int lane = gid & 31;
    if (warp >= BATCH) return;
    const float* xr = g_xhd + (size_t)warp * HD;
    float sc[KPATH];
#pragma unroll
    for (int k = 0; k < KPATH; k++) {
        float s = 0.f;
        for (int h = lane; h < HD; h += 32) s += xr[h] * pb[k * HD + h];
#pragma unroll
        for (int off = 16; off; off >>= 1) s += __shfl_xor_sync(0xffffffffu, s, off);
        sc[k] = s;
    }
    if (lane == 0) {
        float mx = fmaxf(fmaxf(sc[0], sc[1]), fmaxf(sc[2], sc[3]));
        float e0 = expf(sc[0] - mx), e1 = expf(sc[1] - mx);
        float e2 = expf(sc[2] - mx), e3 = expf(sc[3] - mx);
        float inv = 1.0f / (e0 + e1 + e2 + e3);
        g_probs[warp * 4 + 0] = e0 * inv;
        g_probs[warp * 4 + 1] = e1 * inv;
        g_probs[warp * 4 + 2] = e2 * inv;
        g_probs[warp * 4 + 3] = e3 * inv;
    }
}

// ---------------- fp16 mma.sync m16n8k16 GEMM --------------------------------
// C[M,N] = A[M,K] @ Bt[N,K]^T. CTA 128x128, BK=64 fp16 (128B rows, SW128 swizzle).
// 256 threads (8 warps: 4 in M x 2 in N; warp tile 32x64).
#define BM 128
#define BN 128
#define BK 64
#define STAGES 4
#define TILEB (BM * 128)               // 16384 bytes (128B per row)
#define STAGEB (2 * TILEB)             // 32768
#define GEMM_SMEM (STAGES * STAGEB)    // 131072

__device__ __forceinline__ void cp16(uint32_t dst, const void* src) {
    asm volatile("cp.async.cg.shared.global [%0], [%1], 16;"
                 :: "r"(dst), "l"(src) : "memory");
}
__device__ __forceinline__ void cp_commit() {
    asm volatile("cp.async.commit_group;" ::: "memory");
}
template <int N>
__device__ __forceinline__ void cp_wait() {
    asm volatile("cp.async.wait_group %0;" :: "n"(N) : "memory");
}
__device__ __forceinline__ void ldsm4(uint32_t* r, uint32_t addr) {
    asm volatile("ldmatrix.sync.aligned.m8n8.x4.shared.b16 {%0,%1,%2,%3}, [%4];"
                 : "=r"(r[0]), "=r"(r[1]), "=r"(r[2]), "=r"(r[3]) : "r"(addr));
}
__device__ __forceinline__ void mma16816(float* c, const uint32_t* a, const uint32_t* b) {
    asm volatile(
        "mma.sync.aligned.m16n8k16.row.col.f32.f16.f16.f32 "
        "{%0,%1,%2,%3}, {%4,%5,%6,%7}, {%8,%9}, {%0,%1,%2,%3};"
        : "+f"(c[0]), "+f"(c[1]), "+f"(c[2]), "+f"(c[3])
        : "r"(a[0]), "r"(a[1]), "r"(a[2]), "r"(a[3]), "r"(b[0]), "r"(b[1]));
}

__device__ __forceinline__ float gelu_f(float v) {
    // 0.5*v*(1+tanh(u)) = v*sigmoid(2u)
    float u = 1.5957691216057308f * (v + 0.044715f * v * v * v);
    return v * (1.0f / (1.0f + __expf(-u)));
}

// EPI: 0 = plain (OutT half or float), 1 = gelu->half, 2 = bind-accumulate fp32
template <int EPI, typename OutT>
__global__ __launch_bounds__(256)
void tgemm(const __half* __restrict__ A, const __half* __restrict__ Bt,
           OutT* __restrict__ C, int M, int N, int Kd,
           const float* __restrict__ pw, int kpath)
{
    extern __shared__ char smem[];
    uint32_t sbase = (uint32_t)__cvta_generic_to_shared(smem);

    int tid  = threadIdx.x;
    int wid  = tid >> 5;
    int lane = tid & 31;
    int g    = lane >> 2;      // group 0..7
    int tig  = lane & 3;       // thread-in-group
    int wm   = wid & 3;        // warp M index (32 rows)
    int wn   = wid >> 2;       // warp N index (64 cols)

    const __half* Ab = A  + (size_t)blockIdx.y * BM * Kd;
    const __half* Bb = Bt + (size_t)blockIdx.x * BN * Kd;
    int KT = Kd / BK;

    float acc[2][8][4];
#pragma unroll
    for (int i = 0; i < 2; i++)
#pragma unroll
        for (int j = 0; j < 8; j++)
#pragma unroll
            for (int q = 0; q < 4; q++) acc[i][j][q] = 0.f;

    // per-thread ldmatrix address components (swizzle XOR = (row&7)<<4 = (lane&7)<<4)
    uint32_t xm      = (uint32_t)(lane & 7) << 4;
    uint32_t a_row   = (uint32_t)(wm * 32 + (lane & 15)) * 128;
    uint32_t a_klane = (uint32_t)((lane >> 1) & 8) * 2;          // lanes>=16 -> +16B
    int nlo          = (lane & 7) | ((lane & 16) >> 1);
    uint32_t b_klane = (uint32_t)(lane & 8) * 2;                  // lanes 8-15,24-31 -> +16B

    auto load_stage = [&](int stage, int kt) {
        uint32_t abase = sbase + stage * STAGEB;
        uint32_t bbase = abase + TILEB;
        const __half* As = Ab + (size_t)kt * BK;
        const __half* Bs = Bb + (size_t)kt * BK;
#pragma unroll
        for (int i = 0; i < 4; i++) {
            int c   = tid + 256 * i;      // 0..1023
            int row = c >> 3;
            int ch  = c & 7;
            uint32_t off = (uint32_t)row * 128 + (uint32_t)ch * 16;
            uint32_t sw  = off ^ ((off >> 3) & 0x70);
            cp16(abase + sw, As + (size_t)row * Kd + ch * 8);
            cp16(bbase + sw, Bs + (size_t)row * Kd + ch * 8);
        }
    };

#pragma unroll
    for (int s = 0; s < STAGES - 1; s++) {
        if (s < KT) load_stage(s, s);
        cp_commit();
    }

    for (int kt = 0; kt < KT; kt++) {
        cp_wait<STAGES - 2>();
        __syncthreads();

        int nxt = kt + STAGES - 1;
        if (nxt < KT) load_stage(nxt % STAGES, nxt);
        cp_commit();

        uint32_t abase = sbase + (kt % STAGES) * STAGEB;
        uint32_t bbase = abase + TILEB;

#pragma unroll
        for (int ks = 0; ks < 4; ks++) {
            uint32_t kb = (uint32_t)ks * 32;
            uint32_t af[2][4];
#pragma unroll
            for (int mf = 0; mf < 2; mf++)
                ldsm4(af[mf], abase + a_row + (uint32_t)mf * 16 * 128 +
                                ((kb + a_klane) ^ xm));
            uint32_t bf[4][4];
#pragma unroll
            for (int ng = 0; ng < 4; ng++)
                ldsm4(bf[ng], bbase + (uint32_t)(wn * 64 + ng * 16 + nlo) * 128 +
                                ((kb + b_klane) ^ xm));
#pragma unroll
            for (int mf = 0; mf < 2; mf++)
#pragma unroll
                for (int ng = 0; ng < 4; ng++) {
                    mma16816(acc[mf][2 * ng + 0], af[mf], &bf[ng][0]);
                    mma16816(acc[mf][2 * ng + 1], af[mf], &bf[ng][2]);
                }
        }
        __syncthreads();
    }

    // ---- epilogue ----
#pragma unroll
    for (int mf = 0; mf < 2; mf++) {
        int row0 = blockIdx.y * BM + wm * 32 + mf * 16 + g;
#pragma unroll
        for (int half = 0; half < 2; half++) {
            int row = row0 + half * 8;
            float ps0 = 0.f;
            if (EPI == 2) ps0 = g_probs[row * KPATH + kpath];
            OutT* Crow = C + (size_t)row * N;
#pragma unroll
            for (int nf = 0; nf < 8; nf++) {
                int col = blockIdx.x * BN + wn * 64 + (nf >> 1) * 16 + (nf & 1) * 8 + 2 * tig;
                float v0 = acc[mf][nf][half * 2 + 0];
                float v1 = acc[mf][nf][half * 2 + 1];
                if (EPI == 1) { v0 = gelu_f(v0); v1 = gelu_f(v1); }
                if (EPI == 2) {
                    v0 = v0 * ps0 * pw[kpath * HD + col];
                    v1 = v1 * ps0 * pw[kpath * HD + col + 1];
                    if (kpath > 0) {
                        v0 += ((const float*)Crow)[col];
                        v1 += ((const float*)Crow)[col + 1];
                    }
                }
                if (sizeof(OutT) == 2) {
                    __half2 hv = __floats2half2_rn(v0, v1);
                    *(__half2*)((__half*)Crow + col) = hv;
                } else {
                    *(float2*)((float*)Crow + col) = make_float2(v0, v1);
                }
            }
        }
    }
}

// ---------------- launch -----------------------------------------------------
extern "C" void kernel_launch(void* const* d_in, const int* in_sizes, int n_in,
                              void* d_out, int out_size)
{
    const float* x      = (const float*)d_in[0];
    const float* c1a    = (const float*)d_in[1];
    const float* c1b    = (const float*)d_in[2];
    const float* c2a    = (const float*)d_in[3];
    const float* c2b    = (const float*)d_in[4];
    const float* hd_in  = (const float*)d_in[5];
    const float* hd_out = (const float*)d_in[6];
    const float* pb     = (const float*)d_in[7];
    const float* pw     = (const float*)d_in[8];
    float* out = (float*)d_out;

    __half *W1h, *W2h, *hdinTh, *hdoutTh, *xh, *h, *y, *colh;
    float *xhd, *col;
    cudaGetSymbolAddress((void**)&W1h,     g_W1h);
    cudaGetSymbolAddress((void**)&W2h,     g_W2h);
    cudaGetSymbolAddress((void**)&hdinTh,  g_hdinTh);
    cudaGetSymbolAddress((void**)&hdoutTh, g_hdoutTh);
    cudaGetSymbolAddress((void**)&xh,      g_xh);
    cudaGetSymbolAddress((void**)&h,       g_h);
    cudaGetSymbolAddress((void**)&y,       g_y);
    cudaGetSymbolAddress((void**)&colh,    g_colh);
    cudaGetSymbolAddress((void**)&xhd,     g_xhd);
    cudaGetSymbolAddress((void**)&col,     g_col);

    static bool attr_set = false;
    if (!attr_set) {
        cudaFuncSetAttribute(tgemm<0, float>,  cudaFuncAttributeMaxDynamicSharedMemorySize, GEMM_SMEM);
        cudaFuncSetAttribute(tgemm<0, __half>, cudaFuncAttributeMaxDynamicSharedMemorySize, GEMM_SMEM);
        cudaFuncSetAttribute(tgemm<1, __half>, cudaFuncAttributeMaxDynamicSharedMemorySize, GEMM_SMEM);
        cudaFuncSetAttribute(tgemm<2, float>,  cudaFuncAttributeMaxDynamicSharedMemorySize, GEMM_SMEM);
        attr_set = true;
    }

    // 1. build fp16 operands
    build_w1h<<<(KPATH * DFF * DMODEL + 255) / 256, 256>>>(c1a, c1b);
    build_w2h<<<(KPATH * DMODEL * DFF + 255) / 256, 256>>>(c2a, c2b);
    conv_x<<<(BATCH * DMODEL + 255) / 256, 256>>>(x);
    transpose_hdin<<<(DMODEL * HD + 255) / 256, 256>>>(hd_in);
    transpose_hdout<<<(HD * DMODEL + 255) / 256, 256>>>(hd_out);

    // 2. x_hd = x @ hd_in (fp32 out, for routing)
    tgemm<0, float><<<dim3(HD / BN, BATCH / BM), 256, GEMM_SMEM>>>(
        xh, hdinTh, xhd, BATCH, HD, DMODEL, nullptr, 0);

    // 3. routing probs
    routing_kernel<<<(BATCH * 32 + 255) / 256, 256>>>(pb);

    // 4. per-path FFN + bind-accumulate
    for (int k = 0; k < KPATH; k++) {
        tgemm<1, __half><<<dim3(DFF / BN, BATCH / BM), 256, GEMM_SMEM>>>(
            xh, W1h + (size_t)k * DFF * DMODEL, h, BATCH, DFF, DMODEL, nullptr, 0);
        tgemm<0, __half><<<dim3(DMODEL / BN, BATCH / BM), 256, GEMM_SMEM>>>(
            h, W2h + (size_t)k * DMODEL * DFF, y, BATCH, DMODEL, DFF, nullptr, 0);
        tgemm<2, float><<<dim3(HD / BN, BATCH / BM), 256, GEMM_SMEM>>>(
            y, hdinTh, col, BATCH, HD, DMODEL, pw, k);
    }

    // 5. out = col @ hd_out (fp32)
    conv_col<<<(BATCH * HD + 255) / 256, 256>>>();
    tgemm<0, float><<<dim3(DMODEL / BN, BATCH / BM), 256, GEMM_SMEM>>>(
        colh, hdoutTh, out, BATCH, DMODEL, HD, nullptr, 0);
}

// round 5
// speedup vs baseline: 4.1932x; 1.1386x over previous
#include <cuda_runtime.h>
#include <cuda_fp16.h>
#include <math.h>
#include <stdint.h>

// Problem constants
#define BATCH   8192
#define DMODEL  1024
#define DFF     4096
#define KPATH   4
#define RANK    16
#define HD      512

// ---------------- scratch (device globals; no allocation allowed) ----------
__device__ __half g_W1h[KPATH * DFF * DMODEL];   // [k][4096][1024] (N,K) fp16 32MB
__device__ __half g_W2h[KPATH * DMODEL * DFF];   // [k][1024][4096] (N,K) fp16 32MB
__device__ __half g_hdinTh[HD * DMODEL];         // [512][1024] fp16
__device__ __half g_hdoutTh[DMODEL * HD];        // [1024][512] fp16
__device__ __half g_xh[BATCH * DMODEL];          // x in fp16 16MB
__device__ __half g_h[BATCH * DFF];              // 64MB
__device__ __half g_y[BATCH * DMODEL];           // 16MB
__device__ __half g_colh[BATCH * HD];            // 8MB
__device__ float  g_xhd[BATCH * HD];             // fp32 for routing
__device__ float  g_col[BATCH * HD];             // fp32 accumulator
__device__ float  g_probs[BATCH * KPATH];

// ---------------- builders / converters -------------------------------------
__global__ void build_w1h(const float* __restrict__ c1a, const float* __restrict__ c1b) {
    int idx = blockIdx.x * blockDim.x + threadIdx.x;
    if (idx >= KPATH * DFF * DMODEL) return;
    int d  = idx & (DMODEL - 1);          // m*32+p
    int t  = idx >> 10;
    int nn = t & (DFF - 1);               // n*64+o
    int k  = t >> 12;
    int m = d >> 5, p = d & 31;
    int n = nn >> 6, o = nn & 63;
    const float* a = c1a + (((k * 32 + m) * 64 + n) * 16);
    const float* b = c1b + ((size_t)(k * 16) * 32 + p) * 64 + o;
    float s = 0.f;
#pragma unroll
    for (int r = 0; r < RANK; r++) s += a[r] * b[(size_t)r * 32 * 64];
    g_W1h[idx] = __float2half(s);
}

__global__ void build_w2h(const float* __restrict__ c2a, const float* __restrict__ c2b) {
    int idx = blockIdx.x * blockDim.x + threadIdx.x;
    if (idx >= KPATH * DMODEL * DFF) return;
    int d  = idx & (DFF - 1);             // m*64+p
    int t  = idx >> 12;
    int nn = t & (DMODEL - 1);            // n*32+o
    int k  = t >> 10;
    int m = d >> 6, p = d & 63;
    int n = nn >> 5, o = nn & 31;
    const float* a = c2a + (((k * 64 + m) * 32 + n) * 16);
    const float* b = c2b + ((size_t)(k * 16) * 64 + p) * 32 + o;
    float s = 0.f;
#pragma unroll
    for (int r = 0; r < RANK; r++) s += a[r] * b[(size_t)r * 64 * 32];
    g_W2h[idx] = __float2half(s);
}

__global__ void conv_x(const float* __restrict__ x) {
    int i = blockIdx.x * blockDim.x + threadIdx.x;
    if (i < BATCH * DMODEL) g_xh[i] = __float2half(x[i]);
}
__global__ void transpose_hdin(const float* __restrict__ hd_in) {
    int i = blockIdx.x * blockDim.x + threadIdx.x;
    if (i >= DMODEL * HD) return;
    int d = i / HD, h2 = i % HD;
    g_hdinTh[(size_t)h2 * DMODEL + d] = __float2half(hd_in[i]);
}
__global__ void transpose_hdout(const float* __restrict__ hd_out) {
    int i = blockIdx.x * blockDim.x + threadIdx.x;
    if (i >= HD * DMODEL) return;
    int h2 = i / DMODEL, d = i % DMODEL;
    g_hdoutTh[(size_t)d * HD + h2] = __float2half(hd_out[i]);
}
__global__ void conv_col() {
    int i = blockIdx.x * blockDim.x + threadIdx.x;
    if (i < BATCH * HD) g_colh[i] = __float2half(g_col[i]);
}

// ---------------- routing softmax -------------------------------------------
__global__ void routing_kernel(const float* __restrict__ pb) {
    int gid  = blockIdx.x * blockDim.x + threadIdx.x;
    int warp = gid >> 5;
    int lane = gid & 31;
    if (warp >= BATCH) return;
    const float* xr = g_xhd + (size_t)warp * HD;
    float sc[KPATH];
#pragma unroll
    for (int k = 0; k < KPATH; k++) {
        float s = 0.f;
        for (int h = lane; h < HD; h += 32) s += xr[h] * pb[k * HD + h];
#pragma unroll
        for (int off = 16; off; off >>= 1) s += __shfl_xor_sync(0xffffffffu, s, off);
        sc[k] = s;
    }
    if (lane == 0) {
        float mx = fmaxf(fmaxf(sc[0], sc[1]), fmaxf(sc[2], sc[3]));
        float e0 = expf(sc[0] - mx), e1 = expf(sc[1] - mx);
        float e2 = expf(sc[2] - mx), e3 = expf(sc[3] - mx);
        float inv = 1.0f / (e0 + e1 + e2 + e3);
        g_probs[warp * 4 + 0] = e0 * inv;
        g_probs[warp * 4 + 1] = e1 * inv;
        g_probs[warp * 4 + 2] = e2 * inv;
        g_probs[warp * 4 + 3] = e3 * inv;
    }
}

// ---------------- fp16 mma.sync m16n8k16 GEMM --------------------------------
// C[M,N] = A[M,K] @ Bt[N,K]^T. CTA 128x128, BK=64 fp16 (128B rows, SW128 swizzle).
// 256 threads (8 warps: 4 in M x 2 in N; warp tile 32x64). 3-stage pipeline,
// 96KB smem -> 2 CTAs/SM for latency hiding.
#define BM 128
#define BN 128
#define BK 64
#define STAGES 3
#define TILEB (BM * 128)               // 16384 bytes (128B per row)
#define STAGEB (2 * TILEB)             // 32768
#define GEMM_SMEM (STAGES * STAGEB)    // 98304

__device__ __forceinline__ void cp16(uint32_t dst, const void* src) {
    asm volatile("cp.async.cg.shared.global [%0], [%1], 16;"
                 :: "r"(dst), "l"(src) : "memory");
}
__device__ __forceinline__ void cp_commit() {
    asm volatile("cp.async.commit_group;" ::: "memory");
}
template <int N>
__device__ __forceinline__ void cp_wait() {
    asm volatile("cp.async.wait_group %0;" :: "n"(N) : "memory");
}
__device__ __forceinline__ void ldsm4(uint32_t* r, uint32_t addr) {
    asm volatile("ldmatrix.sync.aligned.m8n8.x4.shared.b16 {%0,%1,%2,%3}, [%4];"
                 : "=r"(r[0]), "=r"(r[1]), "=r"(r[2]), "=r"(r[3]) : "r"(addr));
}
__device__ __forceinline__ void mma16816(float* c, const uint32_t* a, const uint32_t* b) {
    asm volatile(
        "mma.sync.aligned.m16n8k16.row.col.f32.f16.f16.f32 "
        "{%0,%1,%2,%3}, {%4,%5,%6,%7}, {%8,%9}, {%0,%1,%2,%3};"
        : "+f"(c[0]), "+f"(c[1]), "+f"(c[2]), "+f"(c[3])
        : "r"(a[0]), "r"(a[1]), "r"(a[2]), "r"(a[3]), "r"(b[0]), "r"(b[1]));
}

__device__ __forceinline__ float gelu_f(float v) {
    // 0.5*v*(1+tanh(u)) = v*sigmoid(2u)
    float u = 1.5957691216057308f * (v + 0.044715f * v * v * v);
    return v * (1.0f / (1.0f + __expf(-u)));
}

// EPI: 0 = plain (OutT half or float), 1 = gelu->half, 2 = bind-accumulate fp32
template <int EPI, typename OutT>
__global__ __launch_bounds__(256, 2)
void tgemm(const __half* __restrict__ A, const __half* __restrict__ Bt,
           OutT* __restrict__ C, int M, int N, int Kd,
           const float* __restrict__ pw, int kpath)
{
    extern __shared__ char smem[];
    uint32_t sbase = (uint32_t)__cvta_generic_to_shared(smem);

    int tid  = threadIdx.x;
    int wid  = tid >> 5;
    int lane = tid & 31;
    int g    = lane >> 2;      // group 0..7
    int tig  = lane & 3;       // thread-in-group
    int wm   = wid & 3;        // warp M index (32 rows)
    int wn   = wid >> 2;       // warp N index (64 cols)

    const __half* Ab = A  + (size_t)blockIdx.y * BM * Kd;
    const __half* Bb = Bt + (size_t)blockIdx.x * BN * Kd;
    int KT = Kd / BK;

    float acc[2][8][4];
#pragma unroll
    for (int i = 0; i < 2; i++)
#pragma unroll
        for (int j = 0; j < 8; j++)
#pragma unroll
            for (int q = 0; q < 4; q++) acc[i][j][q] = 0.f;

    // per-thread ldmatrix address components (swizzle XOR = (row&7)<<4)
    uint32_t xm      = (uint32_t)(lane & 7) << 4;
    uint32_t a_row   = (uint32_t)(wm * 32 + (lane & 15)) * 128;
    uint32_t a_klane = (uint32_t)((lane >> 1) & 8) * 2;          // lanes>=16 -> +16B
    int nlo          = (lane & 7) | ((lane & 16) >> 1);
    uint32_t b_klane = (uint32_t)(lane & 8) * 2;                 // lanes 8-15,24-31 -> +16B

    auto load_stage = [&](int stage, int kt) {
        uint32_t abase = sbase + stage * STAGEB;
        uint32_t bbase = abase + TILEB;
        const __half* As = Ab + (size_t)kt * BK;
        const __half* Bs = Bb + (size_t)kt * BK;
#pragma unroll
        for (int i = 0; i < 4; i++) {
            int c   = tid + 256 * i;      // 0..1023
            int row = c >> 3;
            int ch  = c & 7;
            uint32_t off = (uint32_t)row * 128 + (uint32_t)ch * 16;
            uint32_t sw  = off ^ ((off >> 3) & 0x70);
            cp16(abase + sw, As + (size_t)row * Kd + ch * 8);
            cp16(bbase + sw, Bs + (size_t)row * Kd + ch * 8);
        }
    };

#pragma unroll
    for (int s = 0; s < STAGES - 1; s++) {
        if (s < KT) load_stage(s, s);
        cp_commit();
    }

    for (int kt = 0; kt < KT; kt++) {
        cp_wait<STAGES - 2>();
        __syncthreads();

        int nxt = kt + STAGES - 1;
        if (nxt < KT) load_stage(nxt % STAGES, nxt);
        cp_commit();

        uint32_t abase = sbase + (kt % STAGES) * STAGEB;
        uint32_t bbase = abase + TILEB;

#pragma unroll
        for (int ks = 0; ks < 4; ks++) {
            uint32_t kb = (uint32_t)ks * 32;
            uint32_t af[2][4];
#pragma unroll
            for (int mf = 0; mf < 2; mf++)
                ldsm4(af[mf], abase + a_row + (uint32_t)mf * 16 * 128 +
                                ((kb + a_klane) ^ xm));
            uint32_t bf[4][4];
#pragma unroll
            for (int ng = 0; ng < 4; ng++)
                ldsm4(bf[ng], bbase + (uint32_t)(wn * 64 + ng * 16 + nlo) * 128 +
                                ((kb + b_klane) ^ xm));
#pragma unroll
            for (int mf = 0; mf < 2; mf++)
#pragma unroll
                for (int ng = 0; ng < 4; ng++) {
                    mma16816(acc[mf][2 * ng + 0], af[mf], &bf[ng][0]);
                    mma16816(acc[mf][2 * ng + 1], af[mf], &bf[ng][2]);
                }
        }
        __syncthreads();
    }

    // ---- epilogue ----
#pragma unroll
    for (int mf = 0; mf < 2; mf++) {
        int row0 = blockIdx.y * BM + wm * 32 + mf * 16 + g;
#pragma unroll
        for (int half = 0; half < 2; half++) {
            int row = row0 + half * 8;
            float ps0 = 0.f;
            if (EPI == 2) ps0 = g_probs[row * KPATH + kpath];
            OutT* Crow = C + (size_t)row * N;
#pragma unroll
            for (int nf = 0; nf < 8; nf++) {
                int col = blockIdx.x * BN + wn * 64 + (nf >> 1) * 16 + (nf & 1) * 8 + 2 * tig;
                float v0 = acc[mf][nf][half * 2 + 0];
                float v1 = acc[mf][nf][half * 2 + 1];
                if (EPI == 1) { v0 = gelu_f(v0); v1 = gelu_f(v1); }
                if (EPI == 2) {
                    v0 = v0 * ps0 * pw[kpath * HD + col];
                    v1 = v1 * ps0 * pw[kpath * HD + col + 1];
                    if (kpath > 0) {
                        v0 += ((const float*)Crow)[col];
                        v1 += ((const float*)Crow)[col + 1];
                    }
                }
                if (sizeof(OutT) == 2) {
                    __half2 hv = __floats2half2_rn(v0, v1);
                    *(__half2*)((__half*)Crow + col) = hv;
                } else {
                    *(float2*)((float*)Crow + col) = make_float2(v0, v1);
                }
            }
        }
    }
}

// ---------------- launch -----------------------------------------------------
extern "C" void kernel_launch(void* const* d_in, const int* in_sizes, int n_in,
                              void* d_out, int out_size)
{
    const float* x      = (const float*)d_in[0];
    const float* c1a    = (const float*)d_in[1];
    const float* c1b    = (const float*)d_in[2];
    const float* c2a    = (const float*)d_in[3];
    const float* c2b    = (const float*)d_in[4];
    const float* hd_in  = (const float*)d_in[5];
    const float* hd_out = (const float*)d_in[6];
    const float* pb     = (const float*)d_in[7];
    const float* pw     = (const float*)d_in[8];
    float* out = (float*)d_out;

    __half *W1h, *W2h, *hdinTh, *hdoutTh, *xh, *h, *y, *colh;
    float *xhd, *col;
    cudaGetSymbolAddress((void**)&W1h,     g_W1h);
    cudaGetSymbolAddress((void**)&W2h,     g_W2h);
    cudaGetSymbolAddress((void**)&hdinTh,  g_hdinTh);
    cudaGetSymbolAddress((void**)&hdoutTh, g_hdoutTh);
    cudaGetSymbolAddress((void**)&xh,      g_xh);
    cudaGetSymbolAddress((void**)&h,       g_h);
    cudaGetSymbolAddress((void**)&y,       g_y);
    cudaGetSymbolAddress((void**)&colh,    g_colh);
    cudaGetSymbolAddress((void**)&xhd,     g_xhd);
    cudaGetSymbolAddress((void**)&col,     g_col);

    static bool attr_set = false;
    if (!attr_set) {
        cudaFuncSetAttribute(tgemm<0, float>,  cudaFuncAttributeMaxDynamicSharedMemorySize, GEMM_SMEM);
        cudaFuncSetAttribute(tgemm<0, __half>, cudaFuncAttributeMaxDynamicSharedMemorySize, GEMM_SMEM);
        cudaFuncSetAttribute(tgemm<1, __half>, cudaFuncAttributeMaxDynamicSharedMemorySize, GEMM_SMEM);
        cudaFuncSetAttribute(tgemm<2, float>,  cudaFuncAttributeMaxDynamicSharedMemorySize, GEMM_SMEM);
        attr_set = true;
    }

    // 1. build fp16 operands
    build_w1h<<<(KPATH * DFF * DMODEL + 255) / 256, 256>>>(c1a, c1b);
    build_w2h<<<(KPATH * DMODEL * DFF + 255) / 256, 256>>>(c2a, c2b);
    conv_x<<<(BATCH * DMODEL + 255) / 256, 256>>>(x);
    transpose_hdin<<<(DMODEL * HD + 255) / 256, 256>>>(hd_in);
    transpose_hdout<<<(HD * DMODEL + 255) / 256, 256>>>(hd_out);

    // 2. x_hd = x @ hd_in (fp32 out, for routing)
    tgemm<0, float><<<dim3(HD / BN, BATCH / BM), 256, GEMM_SMEM>>>(
        xh, hdinTh, xhd, BATCH, HD, DMODEL, nullptr, 0);

    // 3. routing probs
    routing_kernel<<<(BATCH * 32 + 255) / 256, 256>>>(pb);

    // 4. per-path FFN + bind-accumulate
    for (int k = 0; k < KPATH; k++) {
        tgemm<1, __half><<<dim3(DFF / BN, BATCH / BM), 256, GEMM_SMEM>>>(
            xh, W1h + (size_t)k * DFF * DMODEL, h, BATCH, DFF, DMODEL, nullptr, 0);
        tgemm<0, __half><<<dim3(DMODEL / BN, BATCH / BM), 256, GEMM_SMEM>>>(
            h, W2h + (size_t)k * DMODEL * DFF, y, BATCH, DMODEL, DFF, nullptr, 0);
        tgemm<2, float><<<dim3(HD / BN, BATCH / BM), 256, GEMM_SMEM>>>(
            y, hdinTh, col, BATCH, HD, DMODEL, pw, k);
    }

    // 5. out = col @ hd_out (fp32)
    conv_col<<<(BATCH * HD + 255) / 256, 256>>>();
    tgemm<0, float><<<dim3(DMODEL / BN, BATCH / BM), 256, GEMM_SMEM>>>(
        colh, hdoutTh, out, BATCH, DMODEL, HD, nullptr, 0);
}